// round 2
// baseline (speedup 1.0000x reference)
#include <cuda_runtime.h>

// Problem constants (fixed by setup_inputs):
// B=16, C=1, H=W=128, WS=8, N = B*WS*WS = 1024 windows, mask all ones.
// Canvas per batch: 1024 x 1024. Output = [canvas (16.7M floats) | windows copy (16.7M floats)].

#define NW        1024          // number of windows
#define BATCH     16
#define WSZ       8
#define CELLS     (WSZ * WSZ)   // 64 cells per batch
#define NTILES    (BATCH * CELLS) // 1024
#define HH        128
#define TILE_PIX  (HH * HH)     // 16384 floats per window/tile
#define TILE_F4   (TILE_PIX / 4)  // 4096 float4 per tile
#define CANV_ROW4 (1024 / 4)    // 256 float4 per canvas row
#define CANV_B4   (1024 * 1024 / 4) // float4 per batch canvas

// Scratch: per-tile window lists (max 64 windows/tile since each tile belongs
// to one batch of 64 windows). __device__ globals — no allocation.
__device__ int            g_tile_count[NTILES];
__device__ unsigned short g_tile_list[NTILES * CELLS];

// ---------------------------------------------------------------------------
// Pass A: one block, 1024 threads. Compute each window's batch via the mask
// row-sum cumsum (replicates searchsorted-right semantics), then bin the
// window index into its tile list. Counts are re-zeroed every launch so the
// kernel is graph-replay safe.
// ---------------------------------------------------------------------------
__global__ void __launch_bounds__(NW) build_lists_kernel(
    const int* __restrict__ positions,   // [NW, 2]
    const int* __restrict__ mask)        // [BATCH, CELLS]
{
    __shared__ int csum[BATCH];
    const int tid = threadIdx.x;

    g_tile_count[tid] = 0;               // NW == NTILES == 1024

    if (tid < BATCH) {
        int s = 0;
        #pragma unroll 8
        for (int j = 0; j < CELLS; ++j) s += mask[tid * CELLS + j];
        csum[tid] = s;
    }
    __syncthreads();
    if (tid == 0) {
        for (int b = 1; b < BATCH; ++b) csum[b] += csum[b - 1];
    }
    __syncthreads();

    const int i = tid;                   // window index
    int b = 0;
    while (b < BATCH && i >= csum[b]) ++b;   // searchsorted(csum, i, 'right')

    const int py = positions[2 * i + 0];
    const int px = positions[2 * i + 1];
    const int tile = (b * WSZ + py) * WSZ + px;

    const int slot = atomicAdd(&g_tile_count[tile], 1);
    g_tile_list[tile * CELLS + slot] = (unsigned short)i;
}

// ---------------------------------------------------------------------------
// Pass B: one block per tile (1024 blocks x 256 threads). Gather-sum the k
// windows of this tile, normalize by 1/(k+1e-6), write the canvas tile, and
// fuse the verbatim windows-copy (each window read exactly once chip-wide).
// All traffic is float4.
// ---------------------------------------------------------------------------
__global__ void __launch_bounds__(256) gather_tiles_kernel(
    const float4* __restrict__ win4,     // windows as float4
    float4* __restrict__ canvas4,        // output canvas (first 16.7M floats)
    float4* __restrict__ copy4)          // output windows copy (second half)
{
    const int tile = blockIdx.x;
    const int k = g_tile_count[tile];

    __shared__ int list[CELLS];
    if (threadIdx.x < k)
        list[threadIdx.x] = g_tile_list[tile * CELLS + threadIdx.x];
    __syncthreads();

    const int b    = tile >> 6;          // /64
    const int cell = tile & 63;
    const int ty   = cell >> 3;
    const int tx   = cell & 7;

    const float inv = 1.0f / ((float)k + 1e-6f);

    // canvas float4 base for this tile: batch offset + top row + left col
    const int cbase = b * CANV_B4 + ty * HH * CANV_ROW4 + tx * (HH / 4);

    #pragma unroll 4
    for (int j = 0; j < TILE_F4 / 256; ++j) {   // 16 iterations
        const int p4 = threadIdx.x + j * 256;   // 0..4095
        const int r  = p4 >> 5;                 // row within tile (32 f4/row)
        const int c4 = p4 & 31;

        float4 s = make_float4(0.f, 0.f, 0.f, 0.f);
        for (int w = 0; w < k; ++w) {
            const int wi = list[w];
            const float4 v = win4[(size_t)wi * TILE_F4 + p4];
            s.x += v.x; s.y += v.y; s.z += v.z; s.w += v.w;
            copy4[(size_t)wi * TILE_F4 + p4] = v;   // fused windows passthrough
        }
        canvas4[cbase + r * CANV_ROW4 + c4] =
            make_float4(s.x * inv, s.y * inv, s.z * inv, s.w * inv);
    }
}

// ---------------------------------------------------------------------------
extern "C" void kernel_launch(void* const* d_in, const int* in_sizes, int n_in,
                              void* d_out, int out_size)
{
    const float* windows   = (const float*)d_in[0];   // [NW,1,128,128] f32
    const int*   positions = (const int*)  d_in[1];   // [NW,2] i32
    const int*   mask      = (const int*)  d_in[2];   // [16,64] i32
    (void)in_sizes; (void)n_in; (void)out_size;

    float* out = (float*)d_out;
    float4* canvas4 = (float4*)out;                        // first 16,777,216 floats
    float4* copy4   = (float4*)(out + (size_t)BATCH * 1024 * 1024); // windows copy

    build_lists_kernel<<<1, NW>>>(positions, mask);
    gather_tiles_kernel<<<NTILES, 256>>>((const float4*)windows, canvas4, copy4);
}

// round 3
// speedup vs baseline: 1.3848x; 1.3848x over previous
#include <cuda_runtime.h>

// Problem constants (fixed by setup_inputs):
// B=16, C=1, H=W=128, WS=8, N = B*WS*WS = 1024 windows, mask all ones.
// Canvas per batch: 1024 x 1024. Output = [canvas (16.7M f32) | windows copy (16.7M f32)].

#define NW        1024            // number of windows
#define BATCH     16
#define WSZ       8
#define CELLS     (WSZ * WSZ)     // 64 cells per batch
#define NTILES    (BATCH * CELLS) // 1024
#define HH        128
#define TILE_PIX  (HH * HH)       // 16384 floats per window/tile
#define TILE_F4   (TILE_PIX / 4)  // 4096 float4 per tile
#define CANV_ROW4 (1024 / 4)      // 256 float4 per canvas row
#define CANV_B4   (1024 * 1024 / 4)

#define GTHREADS  512
#define JPT       (TILE_F4 / GTHREADS)   // 8 float4 per thread

// Scratch: per-tile window lists (each tile can receive at most the 64
// windows of its batch). __device__ globals — no allocation.
__device__ int            g_tile_count[NTILES];
__device__ unsigned short g_tile_list[NTILES * CELLS];

// ---------------------------------------------------------------------------
// Pass A: one block, 1024 threads. Batch assignment via mask-row cumsum
// (searchsorted-right semantics), then bin window index into its tile list.
// Counters re-zeroed every launch -> graph-replay safe.
// ---------------------------------------------------------------------------
__global__ void __launch_bounds__(NW) build_lists_kernel(
    const int* __restrict__ positions,   // [NW, 2]
    const int* __restrict__ mask)        // [BATCH, CELLS]
{
    __shared__ int csum[BATCH];
    const int tid = threadIdx.x;

    g_tile_count[tid] = 0;               // NW == NTILES == 1024

    if (tid < BATCH) {
        int s = 0;
        #pragma unroll 8
        for (int j = 0; j < CELLS; ++j) s += mask[tid * CELLS + j];
        csum[tid] = s;
    }
    __syncthreads();
    if (tid == 0) {
        for (int b = 1; b < BATCH; ++b) csum[b] += csum[b - 1];
    }
    __syncthreads();

    const int i = tid;                   // window index
    int b = 0;
    while (b < BATCH && i >= csum[b]) ++b;   // searchsorted(csum, i, 'right')

    const int py = positions[2 * i + 0];
    const int px = positions[2 * i + 1];
    const int tile = (b * WSZ + py) * WSZ + px;

    const int slot = atomicAdd(&g_tile_count[tile], 1);
    g_tile_list[tile * CELLS + slot] = (unsigned short)i;
}

// ---------------------------------------------------------------------------
// Pass B: one block per tile (1024 blocks x 512 threads). Loop nesting is
// window-outer / pixel-inner-unrolled so each thread keeps 8 independent
// float4 loads in flight (MLP=8) against DRAM latency. Accumulate in regs,
// fuse the verbatim windows copy (each window read exactly once chip-wide),
// then write the normalized canvas tile.
// ---------------------------------------------------------------------------
__global__ void __launch_bounds__(GTHREADS) gather_tiles_kernel(
    const float4* __restrict__ win4,     // windows as float4
    float4* __restrict__ canvas4,        // output canvas (first 16.7M floats)
    float4* __restrict__ copy4)          // output windows copy (second half)
{
    const int tile = blockIdx.x;
    const int k = g_tile_count[tile];

    __shared__ int list[CELLS];
    if (threadIdx.x < k)
        list[threadIdx.x] = g_tile_list[tile * CELLS + threadIdx.x];
    __syncthreads();

    float4 acc[JPT];
    #pragma unroll
    for (int j = 0; j < JPT; ++j)
        acc[j] = make_float4(0.f, 0.f, 0.f, 0.f);

    for (int w = 0; w < k; ++w) {
        const int wi = list[w];
        const float4* __restrict__ src = win4  + (size_t)wi * TILE_F4 + threadIdx.x;
        float4*       __restrict__ dst = copy4 + (size_t)wi * TILE_F4 + threadIdx.x;

        float4 v[JPT];
        #pragma unroll
        for (int j = 0; j < JPT; ++j)           // 8 independent loads in flight
            v[j] = src[j * GTHREADS];
        #pragma unroll
        for (int j = 0; j < JPT; ++j) {
            dst[j * GTHREADS] = v[j];           // fused windows passthrough
            acc[j].x += v[j].x; acc[j].y += v[j].y;
            acc[j].z += v[j].z; acc[j].w += v[j].w;
        }
    }

    const int b    = tile >> 6;
    const int cell = tile & 63;
    const int ty   = cell >> 3;
    const int tx   = cell & 7;
    const float inv = 1.0f / ((float)k + 1e-6f);
    const int cbase = b * CANV_B4 + ty * HH * CANV_ROW4 + tx * (HH / 4);

    #pragma unroll
    for (int j = 0; j < JPT; ++j) {
        const int p4 = threadIdx.x + j * GTHREADS;   // 0..4095
        const int r  = p4 >> 5;                      // 32 f4 per tile row
        const int c4 = p4 & 31;
        canvas4[cbase + r * CANV_ROW4 + c4] =
            make_float4(acc[j].x * inv, acc[j].y * inv,
                        acc[j].z * inv, acc[j].w * inv);
    }
}

// ---------------------------------------------------------------------------
extern "C" void kernel_launch(void* const* d_in, const int* in_sizes, int n_in,
                              void* d_out, int out_size)
{
    const float* windows   = (const float*)d_in[0];   // [NW,1,128,128] f32
    const int*   positions = (const int*)  d_in[1];   // [NW,2] i32
    const int*   mask      = (const int*)  d_in[2];   // [16,64] i32
    (void)in_sizes; (void)n_in; (void)out_size;

    float* out = (float*)d_out;
    float4* canvas4 = (float4*)out;
    float4* copy4   = (float4*)(out + (size_t)BATCH * 1024 * 1024);

    build_lists_kernel<<<1, NW>>>(positions, mask);
    gather_tiles_kernel<<<NTILES, GTHREADS>>>((const float4*)windows, canvas4, copy4);
}

// round 4
// speedup vs baseline: 1.4075x; 1.0164x over previous
#include <cuda_runtime.h>

// Problem constants (fixed by setup_inputs):
// B=16, C=1, H=W=128, WS=8, N = B*WS*WS = 1024 windows, mask all ones.
// Canvas per batch: 1024 x 1024. Output = [canvas (16.7M f32) | windows copy (16.7M f32)].

#define NW        1024            // number of windows
#define BATCH     16
#define WSZ       8
#define CELLS     (WSZ * WSZ)     // 64 cells per batch
#define NTILES    (BATCH * CELLS) // 1024
#define HH        128
#define TILE_PIX  (HH * HH)       // 16384 floats per window/tile
#define TILE_F4   (TILE_PIX / 4)  // 4096 float4 per tile
#define CANV_ROW4 (1024 / 4)      // 256 float4 per canvas row
#define CANV_B4   (1024 * 1024 / 4)

#define GTHREADS  512
#define JPT       (TILE_F4 / GTHREADS)   // 8 float4 per thread

// Scratch: per-tile window lists (each tile can receive at most the 64
// windows of its batch). __device__ globals — no allocation.
__device__ int            g_tile_count[NTILES];
__device__ unsigned short g_tile_list[NTILES * CELLS];

// ---------------------------------------------------------------------------
// Pass A: one block, 1024 threads. Batch assignment via mask-row cumsum
// (searchsorted-right semantics), then bin window index into its tile list.
// Counters re-zeroed every launch -> graph-replay safe.
// ---------------------------------------------------------------------------
__global__ void __launch_bounds__(NW) build_lists_kernel(
    const int* __restrict__ positions,   // [NW, 2]
    const int* __restrict__ mask)        // [BATCH, CELLS]
{
    __shared__ int csum[BATCH];
    const int tid = threadIdx.x;

    g_tile_count[tid] = 0;               // NW == NTILES == 1024

    if (tid < BATCH) {
        int s = 0;
        #pragma unroll 8
        for (int j = 0; j < CELLS; ++j) s += mask[tid * CELLS + j];
        csum[tid] = s;
    }
    __syncthreads();
    if (tid == 0) {
        for (int b = 1; b < BATCH; ++b) csum[b] += csum[b - 1];
    }
    __syncthreads();

    const int i = tid;                   // window index
    int b = 0;
    while (b < BATCH && i >= csum[b]) ++b;   // searchsorted(csum, i, 'right')

    const int py = positions[2 * i + 0];
    const int px = positions[2 * i + 1];
    const int tile = (b * WSZ + py) * WSZ + px;

    const int slot = atomicAdd(&g_tile_count[tile], 1);
    g_tile_list[tile * CELLS + slot] = (unsigned short)i;
}

// ---------------------------------------------------------------------------
// Pass B: one block per tile (1024 blocks x 512 threads). Loop nesting is
// window-outer / pixel-inner-unrolled so each thread keeps 8 independent
// float4 loads in flight (MLP=8) against DRAM latency. Accumulate in regs,
// fuse the verbatim windows copy (each window read exactly once chip-wide),
// then write the normalized canvas tile.
// ---------------------------------------------------------------------------
__global__ void __launch_bounds__(GTHREADS) gather_tiles_kernel(
    const float4* __restrict__ win4,     // windows as float4
    float4* __restrict__ canvas4,        // output canvas (first 16.7M floats)
    float4* __restrict__ copy4)          // output windows copy (second half)
{
    const int tile = blockIdx.x;
    const int k = g_tile_count[tile];

    __shared__ int list[CELLS];
    if (threadIdx.x < k)
        list[threadIdx.x] = g_tile_list[tile * CELLS + threadIdx.x];
    __syncthreads();

    float4 acc[JPT];
    #pragma unroll
    for (int j = 0; j < JPT; ++j)
        acc[j] = make_float4(0.f, 0.f, 0.f, 0.f);

    for (int w = 0; w < k; ++w) {
        const int wi = list[w];
        const float4* __restrict__ src = win4  + (size_t)wi * TILE_F4 + threadIdx.x;
        float4*       __restrict__ dst = copy4 + (size_t)wi * TILE_F4 + threadIdx.x;

        float4 v[JPT];
        #pragma unroll
        for (int j = 0; j < JPT; ++j)           // 8 independent loads in flight
            v[j] = src[j * GTHREADS];
        #pragma unroll
        for (int j = 0; j < JPT; ++j) {
            dst[j * GTHREADS] = v[j];           // fused windows passthrough
            acc[j].x += v[j].x; acc[j].y += v[j].y;
            acc[j].z += v[j].z; acc[j].w += v[j].w;
        }
    }

    const int b    = tile >> 6;
    const int cell = tile & 63;
    const int ty   = cell >> 3;
    const int tx   = cell & 7;
    const float inv = 1.0f / ((float)k + 1e-6f);
    const int cbase = b * CANV_B4 + ty * HH * CANV_ROW4 + tx * (HH / 4);

    #pragma unroll
    for (int j = 0; j < JPT; ++j) {
        const int p4 = threadIdx.x + j * GTHREADS;   // 0..4095
        const int r  = p4 >> 5;                      // 32 f4 per tile row
        const int c4 = p4 & 31;
        canvas4[cbase + r * CANV_ROW4 + c4] =
            make_float4(acc[j].x * inv, acc[j].y * inv,
                        acc[j].z * inv, acc[j].w * inv);
    }
}

// ---------------------------------------------------------------------------
extern "C" void kernel_launch(void* const* d_in, const int* in_sizes, int n_in,
                              void* d_out, int out_size)
{
    const float* windows   = (const float*)d_in[0];   // [NW,1,128,128] f32
    const int*   positions = (const int*)  d_in[1];   // [NW,2] i32
    const int*   mask      = (const int*)  d_in[2];   // [16,64] i32
    (void)in_sizes; (void)n_in; (void)out_size;

    float* out = (float*)d_out;
    float4* canvas4 = (float4*)out;
    float4* copy4   = (float4*)(out + (size_t)BATCH * 1024 * 1024);

    build_lists_kernel<<<1, NW>>>(positions, mask);
    gather_tiles_kernel<<<NTILES, GTHREADS>>>((const float4*)windows, canvas4, copy4);
}